// round 13
// baseline (speedup 1.0000x reference)
#include <cuda_runtime.h>
#include <math.h>

#define NT 192
#define BB 256
#define TT 512

struct Smem {
    // ---- fp64 state & scratch ----
    double Qd[12][12]; double Rd[9][9];
    double x[12]; double P[12][12];
    double xp[12];
    double M[12][12]; double Pp[12][12];
    double PHt[12][9]; double Saug[9][22];   // [S(9) | PHt^T(12) | pad]
    double K[12][9]; double KH[12][12];
    double zp[9]; double innov[9]; double xn[12];
    // ---- fp32: split state, inputs, activations ----
    float xh[12]; float xl[12]; float xph[12]; float xpl[12];
    float uf[4]; float zf[9];
    float a0h[64]; float a0l[64];
    float a1h[64]; float a1l[64];
    float a2h[32]; float a2l[32];
    // ---- weights (fp32, resident) ----
    float dW0[16][64]; float db0[64];
    float dW1[64][64]; float db1[64];
    float dW2[64][32]; float db2[32];
    float dW3[32][12]; float db3[12];
    float mW0[12][64]; float mb0[64];
    float mW1[64][64]; float mb1[64];
    float mW2[64][9];  float mb2[9];
    // ---- fp32 Jacobian-chain scratch ----
    float D0[12][64]; float D1[12][64]; float D2[12][33]; // pad 33
    float F[12][12]; float H[9][12];
};

// TwoSum-based compensated accumulation: (s,c) += p + e, exact on (s,p).
__device__ __forceinline__ void d2acc(float &s, float &c, float p, float e) {
    float t  = s + p;
    float bb = t - s;
    float err = (s - (t - bb)) + (p - bb);
    s = t;
    c += err + e;
}
// accumulate (ah+al)*w into (s,c) with exact product splitting
__device__ __forceinline__ void dotp(float &s, float &c, float ah, float al, float w) {
    float p = ah * w;
    float e = fmaf(ah, w, -p);   // exact tail of ah*w
    e = fmaf(al, w, e);
    d2acc(s, c, p, e);
}
__device__ __forceinline__ double dmerge(float s1, float c1, float s2, float c2) {
    return ((double)s1 + (double)s2) + ((double)c1 + (double)c2);
}
__device__ __forceinline__ void dsplit(double a, float &h, float &l) {
    float hf = (float)a;
    h = hf; l = (float)(a - (double)hf);
}
// float-seeded Newton reciprocal: exact to ~1 ulp fp64, no DDIV
__device__ __forceinline__ double fastrcp(double v) {
    double r = (double)__frcp_rn((float)v);
    r = r * fma(-v, r, 2.0);
    r = r * fma(-v, r, 2.0);
    return r;
}

__global__ void __launch_bounds__(NT, 1) ekf_kernel(
    const float* __restrict__ g_ctl,  const float* __restrict__ g_meas,
    const float* __restrict__ g_x0,   const float* __restrict__ g_P0,
    const float* __restrict__ g_Q,    const float* __restrict__ g_R,
    const float* __restrict__ g_dW0, const float* __restrict__ g_db0,
    const float* __restrict__ g_dW1, const float* __restrict__ g_db1,
    const float* __restrict__ g_dW2, const float* __restrict__ g_db2,
    const float* __restrict__ g_dW3, const float* __restrict__ g_db3,
    const float* __restrict__ g_mW0, const float* __restrict__ g_mb0,
    const float* __restrict__ g_mW1, const float* __restrict__ g_mb1,
    const float* __restrict__ g_mW2, const float* __restrict__ g_mb2,
    float* __restrict__ o_est, float* __restrict__ o_zp, float* __restrict__ o_cov)
{
    extern __shared__ char raw[];
    Smem& s = *reinterpret_cast<Smem*>(raw);
    const int tid = threadIdx.x;
    const int b = blockIdx.x;

    // ---- stage weights & per-batch initial state (round-10 verbatim) ----
    {
        float* d;
        d=&s.dW0[0][0]; for (int i=tid;i<16*64;i+=NT) d[i]=g_dW0[i];
        for (int i=tid;i<64;i+=NT) s.db0[i]=g_db0[i];
        d=&s.dW1[0][0]; for (int i=tid;i<64*64;i+=NT) d[i]=g_dW1[i];
        for (int i=tid;i<64;i+=NT) s.db1[i]=g_db1[i];
        d=&s.dW2[0][0]; for (int i=tid;i<64*32;i+=NT) d[i]=g_dW2[i];
        for (int i=tid;i<32;i+=NT) s.db2[i]=g_db2[i];
        d=&s.dW3[0][0]; for (int i=tid;i<32*12;i+=NT) d[i]=g_dW3[i];
        if (tid<12) s.db3[tid]=g_db3[tid];
        d=&s.mW0[0][0]; for (int i=tid;i<12*64;i+=NT) d[i]=g_mW0[i];
        for (int i=tid;i<64;i+=NT) s.mb0[i]=g_mb0[i];
        d=&s.mW1[0][0]; for (int i=tid;i<64*64;i+=NT) d[i]=g_mW1[i];
        for (int i=tid;i<64;i+=NT) s.mb1[i]=g_mb1[i];
        d=&s.mW2[0][0]; for (int i=tid;i<64*9;i+=NT) d[i]=g_mW2[i];
        if (tid<9) s.mb2[tid]=g_mb2[tid];
        double* q=&s.Qd[0][0]; for (int i=tid;i<144;i+=NT) q[i]=(double)g_Q[i];
        double* r=&s.Rd[0][0]; for (int i=tid;i<81;i+=NT)  r[i]=(double)g_R[i];
        if (tid<12) {
            double xv = (double)g_x0[b*12+tid];
            s.x[tid]=xv; dsplit(xv, s.xh[tid], s.xl[tid]);
        }
        double* p=&s.P[0][0]; for (int i=tid;i<144;i+=NT) p[i]=(double)g_P0[b*144+i];
        if (tid<9) s.zf[tid] = g_meas[((long)b*TT + 0)*9 + tid];
    }
    __syncthreads();

    const int jj  = tid & 63;   // column 0..63
    const int ib3 = tid >> 6;   // 0..2   (rows i = ib3 + 3r, r<4)
    const int j32 = tid & 31;
    const int ib6 = tid >> 5;   // 0..5   (rows i = ib6 + 6r, r<2)

    #pragma unroll 1
    for (int t = 0; t < TT; ++t) {
        if (t > 0) {
            // ===== P1: a0 (thr 0-63)  |  store t-1 outputs (thr 64-191) =====
            if (tid < 64) {
                float s1 = s.db0[tid], c1 = 0.f;
                #pragma unroll
                for (int i=0;i<12;i++) dotp(s1,c1, s.xh[i], s.xl[i], s.dW0[i][tid]);
                #pragma unroll
                for (int i=0;i<4;i++) {
                    float w = s.dW0[12+i][tid];
                    float p = s.uf[i]*w;
                    float e = fmaf(s.uf[i], w, -p);
                    d2acc(s1,c1,p,e);
                }
                double a = tanh((double)s1 + (double)c1);
                dsplit(a, s.a0h[tid], s.a0l[tid]);
            } else {
                long base = (long)b*TT + (t-1);
                const double* Pf = &s.P[0][0];
                for (int e = tid-64; e < 165; e += 128) {
                    if (e < 12)       o_est[base*12 + e]       = (float)s.x[e];
                    else if (e < 21)  o_zp [base*9  + (e-12)]  = (float)s.zp[e-12];
                    else              o_cov[base*144 + (e-21)] = (float)Pf[e-21];
                }
            }
            __syncthreads();
            // ===== P2: D0 (all) + a1 (0-63)  [round-10 verbatim] =====
            {
                float av = s.a0h[jj];
                float g = 1.f - av*av;
                #pragma unroll
                for (int r=0;r<4;r++) s.D0[ib3+3*r][jj] = s.dW0[ib3+3*r][jj]*g;
            }
            if (tid < 64) {
                float s1=s.db1[tid], c1=0.f, s2=0.f, c2=0.f;
                #pragma unroll 8
                for (int k=0;k<64;k+=2) {
                    dotp(s1,c1, s.a0h[k],   s.a0l[k],   s.dW1[k][tid]);
                    dotp(s2,c2, s.a0h[k+1], s.a0l[k+1], s.dW1[k+1][tid]);
                }
                double a = tanh(dmerge(s1,c1,s2,c2));
                dsplit(a, s.a1h[tid], s.a1l[tid]);
            }
            __syncthreads();
            // ===== P3: D1 (all) + a2 (0-31)  [verbatim] =====
            {
                float c0=0,c1=0,c2=0,c3=0;
                #pragma unroll 4
                for (int k=0;k<64;k++) {
                    float w = s.dW1[k][jj];
                    c0 = fmaf(s.D0[ib3+0][k], w, c0);
                    c1 = fmaf(s.D0[ib3+3][k], w, c1);
                    c2 = fmaf(s.D0[ib3+6][k], w, c2);
                    c3 = fmaf(s.D0[ib3+9][k], w, c3);
                }
                float av = s.a1h[jj];
                float g = 1.f - av*av;
                s.D1[ib3+0][jj]=c0*g; s.D1[ib3+3][jj]=c1*g;
                s.D1[ib3+6][jj]=c2*g; s.D1[ib3+9][jj]=c3*g;
            }
            if (tid < 32) {
                float s1=s.db2[tid], c1=0.f, s2=0.f, c2=0.f;
                #pragma unroll 8
                for (int k=0;k<64;k+=2) {
                    dotp(s1,c1, s.a1h[k],   s.a1l[k],   s.dW2[k][tid]);
                    dotp(s2,c2, s.a1h[k+1], s.a1l[k+1], s.dW2[k+1][tid]);
                }
                double a = tanh(dmerge(s1,c1,s2,c2));
                dsplit(a, s.a2h[tid], s.a2l[tid]);
            }
            __syncthreads();
            // ===== P4: D2 (all) + xp (0-11)  [verbatim] =====
            {
                float c0=0,c1=0;
                #pragma unroll 4
                for (int k=0;k<64;k++) {
                    float w = s.dW2[k][j32];
                    c0 = fmaf(s.D1[ib6+0][k], w, c0);
                    c1 = fmaf(s.D1[ib6+6][k], w, c1);
                }
                float av = s.a2h[j32];
                float g = 1.f - av*av;
                s.D2[ib6+0][j32]=c0*g; s.D2[ib6+6][j32]=c1*g;
            }
            if (tid < 12) {
                float s1=s.db3[tid], c1=0.f, s2=0.f, c2=0.f;
                #pragma unroll 8
                for (int k=0;k<32;k+=2) {
                    dotp(s1,c1, s.a2h[k],   s.a2l[k],   s.dW3[k][tid]);
                    dotp(s2,c2, s.a2h[k+1], s.a2l[k+1], s.dW3[k+1][tid]);
                }
                double resid = dmerge(s1,c1,s2,c2);
                double drift = 0.0;
                if (tid < 3)                  drift = s.x[tid+3];
                else if (tid >= 6 && tid < 9) drift = s.x[tid+3];
                double xpv = s.x[tid] + 0.01*drift + resid;
                s.xp[tid] = xpv;
                dsplit(xpv, s.xph[tid], s.xpl[tid]);
            }
            __syncthreads();
        } else {
            // ===== Pinit (t==0): xp = x, Pp = P =====
            if (tid < 12) {
                s.xp[tid] = s.x[tid];
                s.xph[tid] = s.xh[tid]; s.xpl[tid] = s.xl[tid];
            }
            if (tid < 144) { int a=tid/12, j=tid-12*a; s.Pp[a][j] = s.P[a][j]; }
            __syncthreads();
        }

        // ===== P5: a0m (0-63)  |  F (64-191, t>0)  [bodies verbatim] =====
        if (tid < 64) {
            float s1 = s.mb0[tid], c1 = 0.f;
            #pragma unroll
            for (int i=0;i<12;i++) dotp(s1,c1, s.xph[i], s.xpl[i], s.mW0[i][tid]);
            double a = (double)s1 + (double)c1;
            if (a < 0.0) a = 0.0;
            dsplit(a, s.a0h[tid], s.a0l[tid]);
        } else if (t > 0) {
            for (int e = tid-64; e < 144; e += 128) {
                int a = e/12, i = e - 12*a;
                float acc = (a==i) ? 1.f : 0.f;
                if ((a<3 || (a>=6 && a<9)) && i == a+3) acc += 0.01f;
                #pragma unroll 8
                for (int k=0;k<32;k++) acc = fmaf(s.D2[i][k], s.dW3[k][a], acc);
                s.F[a][i] = acc;
            }
        }
        __syncthreads();
        // ===== P6: a1m (0-63)  |  M = F@P (64-191, t>0) =====
        if (tid < 64) {
            float s1=s.mb1[tid], c1=0.f, s2=0.f, c2=0.f;
            #pragma unroll 8
            for (int k=0;k<64;k+=2) {
                dotp(s1,c1, s.a0h[k],   s.a0l[k],   s.mW1[k][tid]);
                dotp(s2,c2, s.a0h[k+1], s.a0l[k+1], s.mW1[k+1][tid]);
            }
            double a = dmerge(s1,c1,s2,c2);
            if (a < 0.0) a = 0.0;
            dsplit(a, s.a1h[tid], s.a1l[tid]);
        } else if (t > 0) {
            for (int e = tid-64; e < 144; e += 128) {
                int a = e/12, j = e - 12*a;
                double acc = 0.0;
                #pragma unroll
                for (int i=0;i<12;i++) acc = fma((double)s.F[a][i], s.P[i][j], acc);
                s.M[a][j] = acc;
            }
        }
        __syncthreads();
        // ===== P7: zp/innov (0-8)  |  Pp = M@F^T + Q (64-191, t>0) =====
        if (tid < 9) {
            float s1=s.mb2[tid], c1=0.f, s2=0.f, c2=0.f;
            #pragma unroll 8
            for (int k=0;k<64;k+=2) {
                dotp(s1,c1, s.a1h[k],   s.a1l[k],   s.mW2[k][tid]);
                dotp(s2,c2, s.a1h[k+1], s.a1l[k+1], s.mW2[k+1][tid]);
            }
            double zpv = s.xp[tid] + dmerge(s1,c1,s2,c2);
            s.zp[tid]    = zpv;
            s.innov[tid] = (double)s.zf[tid] - zpv;
        } else if (tid >= 64 && t > 0) {
            for (int e = tid-64; e < 144; e += 128) {
                int a = e/12, c = e - 12*a;
                double acc = s.Qd[a][c];
                #pragma unroll
                for (int j=0;j<12;j++) acc = fma(s.M[a][j], (double)s.F[c][j], acc);
                s.Pp[a][c] = acc;
            }
        }
        __syncthreads();
        // ===== P8: Dm0 (all)  [verbatim round-10 body] =====
        {
            float g = (s.a0h[jj] > 0.f) ? 1.f : 0.f;
            #pragma unroll
            for (int r=0;r<4;r++) s.D0[ib3+3*r][jj] = s.mW0[ib3+3*r][jj]*g;
        }
        __syncthreads();
        // ===== P9: Dm1 (all)  [verbatim] =====
        {
            float c0=0,c1=0,c2=0,c3=0;
            #pragma unroll 4
            for (int k=0;k<64;k++) {
                float w = s.mW1[k][jj];
                c0 = fmaf(s.D0[ib3+0][k], w, c0);
                c1 = fmaf(s.D0[ib3+3][k], w, c1);
                c2 = fmaf(s.D0[ib3+6][k], w, c2);
                c3 = fmaf(s.D0[ib3+9][k], w, c3);
            }
            float g = (s.a1h[jj] > 0.f) ? 1.f : 0.f;
            s.D1[ib3+0][jj]=c0*g; s.D1[ib3+3][jj]=c1*g;
            s.D1[ib3+6][jj]=c2*g; s.D1[ib3+9][jj]=c3*g;
        }
        __syncthreads();
        // ===== P10: H (0-107)  [verbatim] =====
        if (tid < 108) {
            int a = tid/12, i = tid - 12*a;
            float acc = (a==i) ? 1.f : 0.f;
            #pragma unroll 8
            for (int k=0;k<64;k++) acc = fmaf(s.D1[i][k], s.mW2[k][a], acc);
            s.H[a][i] = acc;
        }
        __syncthreads();
        // ===== P11: PHt = Pp@H^T (+ RHS of Saug) =====
        if (tid < 108) {
            int i = tid/9, a = tid - 9*i;
            double acc = 0.0;
            #pragma unroll
            for (int j=0;j<12;j++) acc = fma(s.Pp[i][j], (double)s.H[a][j], acc);
            s.PHt[i][a] = acc;
            s.Saug[a][9+i] = acc;
        }
        __syncthreads();
        // ===== P12: S = H@PHt + R =====
        if (tid < 81) {
            int a = tid/9, c = tid - 9*a;
            double acc = s.Rd[a][c];
            #pragma unroll
            for (int i=0;i<12;i++) acc = fma((double)s.H[a][i], s.PHt[i][c], acc);
            s.Saug[a][c] = acc;
        }
        __syncthreads();
        // ===== P13: single-warp Gauss-Jordan (warp 0) + K =====
        // Within an iteration: writes touch only rows i!=k, cols c>k;
        // reads of row k / col k untouched -> race-free inside the warp.
        if (tid < 32) {
            double inv = fastrcp(s.Saug[0][0]);
            #pragma unroll 1
            for (int k=0;k<9;k++) {
                const int nc = 20 - k;
                for (int e = tid; e < 8*nc; e += 32) {
                    int i = e / nc; i += (i >= k);
                    int c = k + 1 + (e - (e/nc)*nc);
                    s.Saug[i][c] -= s.Saug[i][k] * inv * s.Saug[k][c];
                }
                __syncwarp();
                if (k < 8) inv = fastrcp(s.Saug[k+1][k+1]);  // final value: col k+1 only updated in iters <= k
            }
            for (int e = tid; e < 108; e += 32) {
                int i = e/9, a = e - 9*i;
                s.K[i][a] = s.Saug[a][9+i] * fastrcp(s.Saug[a][a]);
            }
        }
        __syncthreads();
        // ===== P14: x_new (0-11) ; KH (0-143)  [verbatim] =====
        if (tid < 12) {
            double acc = s.xp[tid];
            #pragma unroll
            for (int a=0;a<9;a++) acc = fma(s.K[tid][a], s.innov[a], acc);
            s.xn[tid] = acc;
        }
        if (tid < 144) {
            int i = tid/12, j = tid - 12*i;
            double acc = 0.0;
            #pragma unroll
            for (int a=0;a<9;a++) acc = fma(s.K[i][a], (double)s.H[a][j], acc);
            s.KH[i][j] = acc;
        }
        __syncthreads();
        // ===== P15: P_new (0-143) ; commit x (0-11) ; load next u,z (156-168) =====
        if (tid < 144) {
            int i = tid/12, j = tid - 12*i;
            double acc = s.Pp[i][j];
            #pragma unroll
            for (int k=0;k<12;k++) acc = fma(-s.KH[i][k], s.Pp[k][j], acc);
            s.P[i][j] = acc;
        }
        if (tid < 12) {
            double xv = s.xn[tid];
            s.x[tid] = xv;
            dsplit(xv, s.xh[tid], s.xl[tid]);
        }
        if (tid >= 156 && tid < 160) {
            if (t+1 < TT) s.uf[tid-156] = g_ctl[((long)b*TT + t+1)*4 + (tid-156)];
        } else if (tid >= 160 && tid < 169) {
            if (t+1 < TT) s.zf[tid-160] = g_meas[((long)b*TT + t+1)*9 + (tid-160)];
        }
        __syncthreads();
    }

    // ---- final store (t = TT-1) ----
    {
        long base = (long)b*TT + (TT-1);
        const double* Pf = &s.P[0][0];
        for (int e = tid; e < 165; e += NT) {
            if (e < 12)       o_est[base*12 + e]       = (float)s.x[e];
            else if (e < 21)  o_zp [base*9  + (e-12)]  = (float)s.zp[e-12];
            else              o_cov[base*144 + (e-21)] = (float)Pf[e-21];
        }
    }
}

extern "C" void kernel_launch(void* const* d_in, const int* in_sizes, int n_in,
                              void* d_out, int out_size)
{
    const float* ctl  = (const float*)d_in[1];
    const float* meas = (const float*)d_in[2];
    const float* x0   = (const float*)d_in[3];
    const float* P0   = (const float*)d_in[4];
    const float* Q    = (const float*)d_in[5];
    const float* R    = (const float*)d_in[6];
    const float* dW0  = (const float*)d_in[7];  const float* db0 = (const float*)d_in[8];
    const float* dW1  = (const float*)d_in[9];  const float* db1 = (const float*)d_in[10];
    const float* dW2  = (const float*)d_in[11]; const float* db2 = (const float*)d_in[12];
    const float* dW3  = (const float*)d_in[13]; const float* db3 = (const float*)d_in[14];
    const float* mW0  = (const float*)d_in[15]; const float* mb0 = (const float*)d_in[16];
    const float* mW1  = (const float*)d_in[17]; const float* mb1 = (const float*)d_in[18];
    const float* mW2  = (const float*)d_in[19]; const float* mb2 = (const float*)d_in[20];

    float* out   = (float*)d_out;
    float* o_est = out;                        // [B,T,12]
    float* o_zp  = out + (long)BB*TT*12;       // [B,T,9]
    float* o_cov = out + (long)BB*TT*(12+9);   // [B,T,12,12]

    int smem = (int)sizeof(Smem);
    cudaFuncSetAttribute(ekf_kernel, cudaFuncAttributeMaxDynamicSharedMemorySize, smem);
    ekf_kernel<<<BB, NT, smem>>>(ctl, meas, x0, P0, Q, R,
        dW0,db0,dW1,db1,dW2,db2,dW3,db3,
        mW0,mb0,mW1,mb1,mW2,mb2,
        o_est, o_zp, o_cov);
}

// round 17
// speedup vs baseline: 1.4669x; 1.4669x over previous
#include <cuda_runtime.h>
#include <math.h>

#define NT 192
#define BB 256
#define TT 512

// ---------- double-single (ds) fp32 arithmetic: ~1e-15 rel precision ----------
struct dsf { float h, l; };
__device__ __forceinline__ dsf ds_norm(float s, float e) {
    float hi = s + e; float lo = e - (hi - s); return {hi, lo};
}
// acc + a*w  (w plain float)
__device__ __forceinline__ dsf ds_fmaf(dsf acc, dsf a, float w) {
    float p = a.h * w;
    float e = fmaf(a.h, w, -p);
    e = fmaf(a.l, w, e);
    float s = acc.h + p;
    float bb = s - acc.h;
    float err = (acc.h - (s - bb)) + (p - bb);
    err += acc.l + e;
    return ds_norm(s, err);
}
__device__ __forceinline__ dsf ds_mul(dsf a, dsf b) {
    float p = a.h * b.h;
    float e = fmaf(a.h, b.h, -p);
    e = fmaf(a.h, b.l, e);
    e = fmaf(a.l, b.h, e);
    return ds_norm(p, e);
}
__device__ __forceinline__ dsf ds_add(dsf a, dsf b) {
    float s = a.h + b.h;
    float bb = s - a.h;
    float err = (a.h - (s - bb)) + (b.h - bb);
    err += a.l + b.l;
    return ds_norm(s, err);
}
__device__ __forceinline__ dsf ds_sub(dsf a, dsf b) { dsf nb = {-b.h, -b.l}; return ds_add(a, nb); }
__device__ __forceinline__ dsf ds_rcp(dsf v) {
    dsf r = { __frcp_rn(v.h), 0.f };
    dsf two = {2.f, 0.f};
    dsf t = ds_mul(v, r); r = ds_mul(r, ds_sub(two, t));
    t = ds_mul(v, r);     r = ds_mul(r, ds_sub(two, t));
    return r;
}
__device__ __forceinline__ double ds2d(dsf a) { return (double)a.h + (double)a.l; }

struct Smem {
    // ---- fp64 x-path state ----
    double x[12]; double xp[12];
    double zp[9]; double innov[9]; double xn[12];
    // ---- ds covariance path ----
    dsf Qf[12][12]; dsf Rf[9][9];
    dsf P[12][12]; dsf M[12][12]; dsf Pp[12][12];
    dsf PHt[12][9]; dsf Saug[9][22];   // [S(9) | PHt^T(12) | pad]
    dsf K[12][9]; dsf KH[12][12]; dsf rdiag[9];
    // ---- fp32: split state, inputs, activations ----
    float xh[12]; float xl[12]; float xph[12]; float xpl[12];
    float uf[4]; float zf[9];
    float a0h[64]; float a0l[64];
    float a1h[64]; float a1l[64];
    float a2h[32]; float a2l[32];
    // ---- weights (fp32, resident) ----
    float dW0[16][64]; float db0[64];
    float dW1[64][64]; float db1[64];
    float dW2[64][32]; float db2[32];
    float dW3[32][12]; float db3[12];
    float mW0[12][64]; float mb0[64];
    float mW1[64][64]; float mb1[64];
    float mW2[64][9];  float mb2[9];
    // ---- fp32 Jacobian-chain scratch ----
    float D0[12][64]; float D1[12][64]; float D2[12][33]; // pad 33
    float F[12][12]; float H[9][12];
};

// TwoSum-based compensated accumulation (x-path dots; round-10 verbatim)
__device__ __forceinline__ void d2acc(float &s, float &c, float p, float e) {
    float t  = s + p;
    float bb = t - s;
    float err = (s - (t - bb)) + (p - bb);
    s = t;
    c += err + e;
}
__device__ __forceinline__ void dotp(float &s, float &c, float ah, float al, float w) {
    float p = ah * w;
    float e = fmaf(ah, w, -p);
    e = fmaf(al, w, e);
    d2acc(s, c, p, e);
}
__device__ __forceinline__ double dmerge(float s1, float c1, float s2, float c2) {
    return ((double)s1 + (double)s2) + ((double)c1 + (double)c2);
}
__device__ __forceinline__ void dsplit(double a, float &h, float &l) {
    float hf = (float)a;
    h = hf; l = (float)(a - (double)hf);
}

__global__ void __launch_bounds__(NT, 1) ekf_kernel(
    const float* __restrict__ g_ctl,  const float* __restrict__ g_meas,
    const float* __restrict__ g_x0,   const float* __restrict__ g_P0,
    const float* __restrict__ g_Q,    const float* __restrict__ g_R,
    const float* __restrict__ g_dW0, const float* __restrict__ g_db0,
    const float* __restrict__ g_dW1, const float* __restrict__ g_db1,
    const float* __restrict__ g_dW2, const float* __restrict__ g_db2,
    const float* __restrict__ g_dW3, const float* __restrict__ g_db3,
    const float* __restrict__ g_mW0, const float* __restrict__ g_mb0,
    const float* __restrict__ g_mW1, const float* __restrict__ g_mb1,
    const float* __restrict__ g_mW2, const float* __restrict__ g_mb2,
    float* __restrict__ o_est, float* __restrict__ o_zp, float* __restrict__ o_cov)
{
    extern __shared__ char raw[];
    Smem& s = *reinterpret_cast<Smem*>(raw);
    const int tid = threadIdx.x;
    const int b = blockIdx.x;

    // ---- stage weights & per-batch initial state ----
    {
        float* d;
        d=&s.dW0[0][0]; for (int i=tid;i<16*64;i+=NT) d[i]=g_dW0[i];
        for (int i=tid;i<64;i+=NT) s.db0[i]=g_db0[i];
        d=&s.dW1[0][0]; for (int i=tid;i<64*64;i+=NT) d[i]=g_dW1[i];
        for (int i=tid;i<64;i+=NT) s.db1[i]=g_db1[i];
        d=&s.dW2[0][0]; for (int i=tid;i<64*32;i+=NT) d[i]=g_dW2[i];
        for (int i=tid;i<32;i+=NT) s.db2[i]=g_db2[i];
        d=&s.dW3[0][0]; for (int i=tid;i<32*12;i+=NT) d[i]=g_dW3[i];
        if (tid<12) s.db3[tid]=g_db3[tid];
        d=&s.mW0[0][0]; for (int i=tid;i<12*64;i+=NT) d[i]=g_mW0[i];
        for (int i=tid;i<64;i+=NT) s.mb0[i]=g_mb0[i];
        d=&s.mW1[0][0]; for (int i=tid;i<64*64;i+=NT) d[i]=g_mW1[i];
        for (int i=tid;i<64;i+=NT) s.mb1[i]=g_mb1[i];
        d=&s.mW2[0][0]; for (int i=tid;i<64*9;i+=NT) d[i]=g_mW2[i];
        if (tid<9) s.mb2[tid]=g_mb2[tid];
        { dsf* q=&s.Qf[0][0]; for (int i=tid;i<144;i+=NT) q[i]={g_Q[i],0.f}; }
        { dsf* r=&s.Rf[0][0]; for (int i=tid;i<81;i+=NT)  r[i]={g_R[i],0.f}; }
        if (tid<12) {
            double xv = (double)g_x0[b*12+tid];
            s.x[tid]=xv; dsplit(xv, s.xh[tid], s.xl[tid]);
        }
        { dsf* p=&s.P[0][0]; for (int i=tid;i<144;i+=NT) p[i]={g_P0[b*144+i],0.f}; }
        if (tid<9) s.zf[tid] = g_meas[((long)b*TT + 0)*9 + tid];
    }
    __syncthreads();

    const int jj  = tid & 63;   // column 0..63
    const int ib3 = tid >> 6;   // 0..2   (rows i = ib3 + 3r, r<4)
    const int j32 = tid & 31;
    const int ib6 = tid >> 5;   // 0..5   (rows i = ib6 + 6r, r<2)

    #pragma unroll 1
    for (int t = 0; t < TT; ++t) {
        if (t > 0) {
            // ===== P1: a0 (thr 0-63)  |  store t-1 outputs (thr 64-191) =====
            if (tid < 64) {
                float s1 = s.db0[tid], c1 = 0.f;
                #pragma unroll
                for (int i=0;i<12;i++) dotp(s1,c1, s.xh[i], s.xl[i], s.dW0[i][tid]);
                #pragma unroll
                for (int i=0;i<4;i++) {
                    float w = s.dW0[12+i][tid];
                    float p = s.uf[i]*w;
                    float e = fmaf(s.uf[i], w, -p);
                    d2acc(s1,c1,p,e);
                }
                double a = tanh((double)s1 + (double)c1);
                dsplit(a, s.a0h[tid], s.a0l[tid]);
            } else {
                long base = (long)b*TT + (t-1);
                const dsf* Pf = &s.P[0][0];
                for (int e = tid-64; e < 165; e += 128) {
                    if (e < 12)       o_est[base*12 + e]       = (float)s.x[e];
                    else if (e < 21)  o_zp [base*9  + (e-12)]  = (float)s.zp[e-12];
                    else              o_cov[base*144 + (e-21)] = Pf[e-21].h;
                }
            }
            __syncthreads();
            // ===== P2: D0 (all) + a1 (0-63) =====
            {
                float av = s.a0h[jj];
                float g = 1.f - av*av;
                #pragma unroll
                for (int r=0;r<4;r++) s.D0[ib3+3*r][jj] = s.dW0[ib3+3*r][jj]*g;
            }
            if (tid < 64) {
                float s1=s.db1[tid], c1=0.f, s2=0.f, c2=0.f;
                #pragma unroll 8
                for (int k=0;k<64;k+=2) {
                    dotp(s1,c1, s.a0h[k],   s.a0l[k],   s.dW1[k][tid]);
                    dotp(s2,c2, s.a0h[k+1], s.a0l[k+1], s.dW1[k+1][tid]);
                }
                double a = tanh(dmerge(s1,c1,s2,c2));
                dsplit(a, s.a1h[tid], s.a1l[tid]);
            }
            __syncthreads();
            // ===== P3: D1 (all) + a2 (0-31) =====
            {
                float c0=0,c1=0,c2=0,c3=0;
                #pragma unroll 4
                for (int k=0;k<64;k++) {
                    float w = s.dW1[k][jj];
                    c0 = fmaf(s.D0[ib3+0][k], w, c0);
                    c1 = fmaf(s.D0[ib3+3][k], w, c1);
                    c2 = fmaf(s.D0[ib3+6][k], w, c2);
                    c3 = fmaf(s.D0[ib3+9][k], w, c3);
                }
                float av = s.a1h[jj];
                float g = 1.f - av*av;
                s.D1[ib3+0][jj]=c0*g; s.D1[ib3+3][jj]=c1*g;
                s.D1[ib3+6][jj]=c2*g; s.D1[ib3+9][jj]=c3*g;
            }
            if (tid < 32) {
                float s1=s.db2[tid], c1=0.f, s2=0.f, c2=0.f;
                #pragma unroll 8
                for (int k=0;k<64;k+=2) {
                    dotp(s1,c1, s.a1h[k],   s.a1l[k],   s.dW2[k][tid]);
                    dotp(s2,c2, s.a1h[k+1], s.a1l[k+1], s.dW2[k+1][tid]);
                }
                double a = tanh(dmerge(s1,c1,s2,c2));
                dsplit(a, s.a2h[tid], s.a2l[tid]);
            }
            __syncthreads();
            // ===== P4: D2 (all) + xp (0-11) =====
            {
                float c0=0,c1=0;
                #pragma unroll 4
                for (int k=0;k<64;k++) {
                    float w = s.dW2[k][j32];
                    c0 = fmaf(s.D1[ib6+0][k], w, c0);
                    c1 = fmaf(s.D1[ib6+6][k], w, c1);
                }
                float av = s.a2h[j32];
                float g = 1.f - av*av;
                s.D2[ib6+0][j32]=c0*g; s.D2[ib6+6][j32]=c1*g;
            }
            if (tid < 12) {
                float s1=s.db3[tid], c1=0.f, s2=0.f, c2=0.f;
                #pragma unroll 8
                for (int k=0;k<32;k+=2) {
                    dotp(s1,c1, s.a2h[k],   s.a2l[k],   s.dW3[k][tid]);
                    dotp(s2,c2, s.a2h[k+1], s.a2l[k+1], s.dW3[k+1][tid]);
                }
                double resid = dmerge(s1,c1,s2,c2);
                double drift = 0.0;
                if (tid < 3)                  drift = s.x[tid+3];
                else if (tid >= 6 && tid < 9) drift = s.x[tid+3];
                double xpv = s.x[tid] + 0.01*drift + resid;
                s.xp[tid] = xpv;
                dsplit(xpv, s.xph[tid], s.xpl[tid]);
            }
            __syncthreads();
        } else {
            // ===== Pinit (t==0): xp = x, Pp = P =====
            if (tid < 12) {
                s.xp[tid] = s.x[tid];
                s.xph[tid] = s.xh[tid]; s.xpl[tid] = s.xl[tid];
            }
            if (tid < 144) { int a=tid/12, j=tid-12*a; s.Pp[a][j] = s.P[a][j]; }
            __syncthreads();
        }

        // ===== P5: a0m (0-63)  |  F (64-191, t>0) =====
        if (tid < 64) {
            float s1 = s.mb0[tid], c1 = 0.f;
            #pragma unroll
            for (int i=0;i<12;i++) dotp(s1,c1, s.xph[i], s.xpl[i], s.mW0[i][tid]);
            double a = (double)s1 + (double)c1;
            if (a < 0.0) a = 0.0;
            dsplit(a, s.a0h[tid], s.a0l[tid]);
        } else if (t > 0) {
            for (int e = tid-64; e < 144; e += 128) {
                int a = e/12, i = e - 12*a;
                float acc = (a==i) ? 1.f : 0.f;
                if ((a<3 || (a>=6 && a<9)) && i == a+3) acc += 0.01f;
                #pragma unroll 8
                for (int k=0;k<32;k++) acc = fmaf(s.D2[i][k], s.dW3[k][a], acc);
                s.F[a][i] = acc;
            }
        }
        __syncthreads();
        // ===== P6: a1m (0-63)  |  M = F@P (64-191, t>0, ds) =====
        if (tid < 64) {
            float s1=s.mb1[tid], c1=0.f, s2=0.f, c2=0.f;
            #pragma unroll 8
            for (int k=0;k<64;k+=2) {
                dotp(s1,c1, s.a0h[k],   s.a0l[k],   s.mW1[k][tid]);
                dotp(s2,c2, s.a0h[k+1], s.a0l[k+1], s.mW1[k+1][tid]);
            }
            double a = dmerge(s1,c1,s2,c2);
            if (a < 0.0) a = 0.0;
            dsplit(a, s.a1h[tid], s.a1l[tid]);
        } else if (t > 0) {
            for (int e = tid-64; e < 144; e += 128) {
                int a = e/12, j = e - 12*a;
                dsf acc = {0.f, 0.f};
                #pragma unroll
                for (int i=0;i<12;i++) acc = ds_fmaf(acc, s.P[i][j], s.F[a][i]);
                s.M[a][j] = acc;
            }
        }
        __syncthreads();
        // ===== P7: zp/innov (0-8)  |  Pp = M@F^T + Q (64-191, t>0, ds) =====
        if (tid < 9) {
            float s1=s.mb2[tid], c1=0.f, s2=0.f, c2=0.f;
            #pragma unroll 8
            for (int k=0;k<64;k+=2) {
                dotp(s1,c1, s.a1h[k],   s.a1l[k],   s.mW2[k][tid]);
                dotp(s2,c2, s.a1h[k+1], s.a1l[k+1], s.mW2[k+1][tid]);
            }
            double zpv = s.xp[tid] + dmerge(s1,c1,s2,c2);
            s.zp[tid]    = zpv;
            s.innov[tid] = (double)s.zf[tid] - zpv;
        } else if (tid >= 64 && t > 0) {
            for (int e = tid-64; e < 144; e += 128) {
                int a = e/12, c = e - 12*a;
                dsf acc = s.Qf[a][c];
                #pragma unroll
                for (int j=0;j<12;j++) acc = ds_fmaf(acc, s.M[a][j], s.F[c][j]);
                s.Pp[a][c] = acc;
            }
        }
        __syncthreads();
        // ===== P8: Dm0 (all) =====
        {
            float g = (s.a0h[jj] > 0.f) ? 1.f : 0.f;
            #pragma unroll
            for (int r=0;r<4;r++) s.D0[ib3+3*r][jj] = s.mW0[ib3+3*r][jj]*g;
        }
        __syncthreads();
        // ===== P9: Dm1 (all) =====
        {
            float c0=0,c1=0,c2=0,c3=0;
            #pragma unroll 4
            for (int k=0;k<64;k++) {
                float w = s.mW1[k][jj];
                c0 = fmaf(s.D0[ib3+0][k], w, c0);
                c1 = fmaf(s.D0[ib3+3][k], w, c1);
                c2 = fmaf(s.D0[ib3+6][k], w, c2);
                c3 = fmaf(s.D0[ib3+9][k], w, c3);
            }
            float g = (s.a1h[jj] > 0.f) ? 1.f : 0.f;
            s.D1[ib3+0][jj]=c0*g; s.D1[ib3+3][jj]=c1*g;
            s.D1[ib3+6][jj]=c2*g; s.D1[ib3+9][jj]=c3*g;
        }
        __syncthreads();
        // ===== P10: H (0-107) =====
        if (tid < 108) {
            int a = tid/12, i = tid - 12*a;
            float acc = (a==i) ? 1.f : 0.f;
            #pragma unroll 8
            for (int k=0;k<64;k++) acc = fmaf(s.D1[i][k], s.mW2[k][a], acc);
            s.H[a][i] = acc;
        }
        __syncthreads();
        // ===== P11: PHt = Pp@H^T (ds) (+ RHS of Saug) =====
        if (tid < 108) {
            int i = tid/9, a = tid - 9*i;
            dsf acc = {0.f, 0.f};
            #pragma unroll
            for (int j=0;j<12;j++) acc = ds_fmaf(acc, s.Pp[i][j], s.H[a][j]);
            s.PHt[i][a] = acc;
            s.Saug[a][9+i] = acc;
        }
        __syncthreads();
        // ===== P12: S = H@PHt + R (ds); rdiag[0] =====
        if (tid < 81) {
            int a = tid/9, c = tid - 9*a;
            dsf acc = s.Rf[a][c];
            #pragma unroll
            for (int i=0;i<12;i++) acc = ds_fmaf(acc, s.PHt[i][c], s.H[a][i]);
            s.Saug[a][c] = acc;
            if (tid == 0) s.rdiag[0] = ds_rcp(acc);
        }
        __syncthreads();
        // ===== GJ: unpivoted Gauss-Jordan on SPD S (ds, block-wide spread) =====
        #pragma unroll 1
        for (int k=0;k<9;k++) {
            const int nc = 20 - k;
            const dsf inv = s.rdiag[k];
            for (int e = tid; e < 8*nc; e += NT) {
                int i = e / nc; i += (i >= k);
                int c = k + 1 + (e - (e/nc)*nc);
                dsf v = ds_sub(s.Saug[i][c], ds_mul(s.Saug[i][k], ds_mul(inv, s.Saug[k][c])));
                s.Saug[i][c] = v;
                if (i == k+1 && c == k+1) s.rdiag[k+1] = ds_rcp(v);
            }
            __syncthreads();
        }
        // ===== P20: K (ds, no division) =====
        if (tid < 108) {
            int i = tid/9, a = tid - 9*i;
            s.K[i][a] = ds_mul(s.Saug[a][9+i], s.rdiag[a]);
        }
        __syncthreads();
        // ===== P21: x_new (fp64, 0-11) ; KH (ds, 0-143) =====
        if (tid < 12) {
            double acc = s.xp[tid];
            #pragma unroll
            for (int a=0;a<9;a++) acc = fma(ds2d(s.K[tid][a]), s.innov[a], acc);
            s.xn[tid] = acc;
        }
        if (tid < 144) {
            int i = tid/12, j = tid - 12*i;
            dsf acc = {0.f, 0.f};
            #pragma unroll
            for (int a=0;a<9;a++) acc = ds_fmaf(acc, s.K[i][a], s.H[a][j]);
            s.KH[i][j] = acc;
        }
        __syncthreads();
        // ===== P22: P_new = Pp - KH@Pp (ds) ; commit x ; load next u,z =====
        if (tid < 144) {
            int i = tid/12, j = tid - 12*i;
            dsf acc = {0.f, 0.f};
            #pragma unroll
            for (int k=0;k<12;k++) acc = ds_add(acc, ds_mul(s.KH[i][k], s.Pp[k][j]));
            s.P[i][j] = ds_sub(s.Pp[i][j], acc);
        }
        if (tid < 12) {
            double xv = s.xn[tid];
            s.x[tid] = xv;
            dsplit(xv, s.xh[tid], s.xl[tid]);
        }
        if (tid >= 156 && tid < 160) {
            if (t+1 < TT) s.uf[tid-156] = g_ctl[((long)b*TT + t+1)*4 + (tid-156)];
        } else if (tid >= 160 && tid < 169) {
            if (t+1 < TT) s.zf[tid-160] = g_meas[((long)b*TT + t+1)*9 + (tid-160)];
        }
        __syncthreads();
    }

    // ---- final store (t = TT-1) ----
    {
        long base = (long)b*TT + (TT-1);
        const dsf* Pf = &s.P[0][0];
        for (int e = tid; e < 165; e += NT) {
            if (e < 12)       o_est[base*12 + e]       = (float)s.x[e];
            else if (e < 21)  o_zp [base*9  + (e-12)]  = (float)s.zp[e-12];
            else              o_cov[base*144 + (e-21)] = Pf[e-21].h;
        }
    }
}

extern "C" void kernel_launch(void* const* d_in, const int* in_sizes, int n_in,
                              void* d_out, int out_size)
{
    const float* ctl  = (const float*)d_in[1];
    const float* meas = (const float*)d_in[2];
    const float* x0   = (const float*)d_in[3];
    const float* P0   = (const float*)d_in[4];
    const float* Q    = (const float*)d_in[5];
    const float* R    = (const float*)d_in[6];
    const float* dW0  = (const float*)d_in[7];  const float* db0 = (const float*)d_in[8];
    const float* dW1  = (const float*)d_in[9];  const float* db1 = (const float*)d_in[10];
    const float* dW2  = (const float*)d_in[11]; const float* db2 = (const float*)d_in[12];
    const float* dW3  = (const float*)d_in[13]; const float* db3 = (const float*)d_in[14];
    const float* mW0  = (const float*)d_in[15]; const float* mb0 = (const float*)d_in[16];
    const float* mW1  = (const float*)d_in[17]; const float* mb1 = (const float*)d_in[18];
    const float* mW2  = (const float*)d_in[19]; const float* mb2 = (const float*)d_in[20];

    float* out   = (float*)d_out;
    float* o_est = out;                        // [B,T,12]
    float* o_zp  = out + (long)BB*TT*12;       // [B,T,9]
    float* o_cov = out + (long)BB*TT*(12+9);   // [B,T,12,12]

    int smem = (int)sizeof(Smem);
    cudaFuncSetAttribute(ekf_kernel, cudaFuncAttributeMaxDynamicSharedMemorySize, smem);
    ekf_kernel<<<BB, NT, smem>>>(ctl, meas, x0, P0, Q, R,
        dW0,db0,dW1,db1,dW2,db2,dW3,db3,
        mW0,mb0,mW1,mb1,mW2,mb2,
        o_est, o_zp, o_cov);
}